// round 16
// baseline (speedup 1.0000x reference)
#include <cuda_runtime.h>
#include <cuda_bf16.h>
#include <math.h>
#include <stdint.h>

// ---------------- problem constants ----------------
#define VOCAB 32000
#define EMB   512
#define SEQ   2048
#define NHEAD 8
#define NLAYER 6
#define FFDIM 2048
#define BATCH 2
#define HEADD 64
#define BT    (BATCH*SEQ)      // 4096 tokens
#define EPS_LN 1e-5f

// ---------------- scratch (device globals; no allocation allowed) ----------------
__device__ float    g_h  [BT*EMB];     // residual stream (fp32)
__device__ uint32_t g_y  [BT*EMB];     // LN output (tf32)
__device__ uint32_t g_q  [BT*EMB];     // tf32, pre-scaled by 0.125
__device__ uint32_t g_k  [BT*EMB];     // tf32
__device__ uint32_t g_v  [BT*EMB];     // tf32
__device__ uint32_t g_o  [BT*EMB];     // attention output (tf32)
__device__ uint32_t g_ff [BT*FFDIM];   // FFN hidden (tf32)
__device__ uint32_t g_htf[BT*EMB];     // final residual (tf32) for vocab gemm

// tf32 weight mirror, same [K][N] layout as inputs
#define EE6 (NLAYER*EMB*EMB)
#define EF6 (NLAYER*EMB*FFDIM)
#define OFF_WQ   0
#define OFF_WK   (EE6)
#define OFF_WV   (2*EE6)
#define OFF_WO   (3*EE6)
#define OFF_W1   (4*EE6)
#define OFF_W2   (4*EE6 + EF6)
#define OFF_WOUT (4*EE6 + 2*EF6)
#define WTF_TOTAL (4*EE6 + 2*EF6 + EMB*VOCAB)
__device__ uint32_t g_wtf[WTF_TOTAL];

#define EMBED_BLOCKS 2048
#define CVT_BLOCKS   (WTF_TOTAL/1024)

// ---------------- helpers ----------------
__device__ __forceinline__ uint32_t f2tf(float f) {
    uint32_t u; asm("cvt.rna.tf32.f32 %0, %1;" : "=r"(u) : "f"(f)); return u;
}
__device__ __forceinline__ void mma_tf32(float* c, const uint32_t* a, const uint32_t* b) {
    asm volatile(
        "mma.sync.aligned.m16n8k8.row.col.f32.tf32.tf32.f32 "
        "{%0,%1,%2,%3}, {%4,%5,%6,%7}, {%8,%9}, {%0,%1,%2,%3};\n"
        : "+f"(c[0]), "+f"(c[1]), "+f"(c[2]), "+f"(c[3])
        : "r"(a[0]), "r"(a[1]), "r"(a[2]), "r"(a[3]),
          "r"(b[0]), "r"(b[1]));
}
__device__ __forceinline__ uint32_t smem_u32(const void* p) {
    uint32_t a;
    asm("{ .reg .u64 t; cvta.to.shared.u64 t, %1; cvt.u32.u64 %0, t; }" : "=r"(a) : "l"(p));
    return a;
}
#define CP_ASYNC16(dst, src) \
    asm volatile("cp.async.cg.shared.global [%0], [%1], 16;" :: "r"(dst), "l"(src))
#define CP_COMMIT() asm volatile("cp.async.commit_group;" ::: "memory")
#define CP_WAIT1()  asm volatile("cp.async.wait_group 1;" ::: "memory")
#define CP_WAIT0()  asm volatile("cp.async.wait_group 0;" ::: "memory")

// ---------------- fused prep: weight convert + embedding ----------------
__global__ void prep_kernel(
    const float* __restrict__ Wq, const float* __restrict__ Wk,
    const float* __restrict__ Wv, const float* __restrict__ Wo,
    const float* __restrict__ W1, const float* __restrict__ W2,
    const float* __restrict__ Wout, uint32_t* __restrict__ d,
    const int* __restrict__ x, const float* __restrict__ tok,
    const float* __restrict__ pos, float* __restrict__ h)
{
    if (blockIdx.x < EMBED_BLOCKS) {
        size_t i = ((size_t)blockIdx.x * 256 + threadIdx.x) * 4;
        int row = (int)(i >> 9);
        int col = (int)(i & 511);
        int t   = row % SEQ;
        int id  = x[row];
        float4 a = *(const float4*)&tok[(size_t)id * EMB + col];
        float4 b = *(const float4*)&pos[(size_t)t  * EMB + col];
        float4 r = { a.x + b.x, a.y + b.y, a.z + b.z, a.w + b.w };
        *(float4*)&h[i] = r;
        return;
    }
    size_t i = ((size_t)(blockIdx.x - EMBED_BLOCKS) * 256 + threadIdx.x) * 4;
    if (i >= WTF_TOTAL) return;
    const float* s; size_t loc;
    if      (i < OFF_WK)   { s = Wq;   loc = i;            }
    else if (i < OFF_WV)   { s = Wk;   loc = i - OFF_WK;   }
    else if (i < OFF_WO)   { s = Wv;   loc = i - OFF_WV;   }
    else if (i < OFF_W1)   { s = Wo;   loc = i - OFF_WO;   }
    else if (i < OFF_W2)   { s = W1;   loc = i - OFF_W1;   }
    else if (i < OFF_WOUT) { s = W2;   loc = i - OFF_W2;   }
    else                   { s = Wout; loc = i - OFF_WOUT; }
    float4 v = *(const float4*)&s[loc];
    uint4 u = { f2tf(v.x), f2tf(v.y), f2tf(v.z), f2tf(v.w) };
    *(uint4*)&d[i] = u;
}

// ---------------- layernorm: one warp per row, shuffle-only ----------------
__global__ __launch_bounds__(256) void ln_kernel(
    const float* __restrict__ X,
    const float* __restrict__ scale,
    const float* __restrict__ bias,
    uint32_t* __restrict__ Y)
{
    const int warp = threadIdx.x >> 5, lane = threadIdx.x & 31;
    const int row  = blockIdx.x * 8 + warp;
    const float* x = X + (size_t)row * EMB;
    uint32_t*    y = Y + (size_t)row * EMB;

    float4 v[4];
    float s = 0.f, sq = 0.f;
    #pragma unroll
    for (int i = 0; i < 4; i++) {
        v[i] = *(const float4*)&x[lane*4 + i*128];
        s  += v[i].x + v[i].y + v[i].z + v[i].w;
        sq += v[i].x*v[i].x + v[i].y*v[i].y + v[i].z*v[i].z + v[i].w*v[i].w;
    }
    #pragma unroll
    for (int d = 16; d > 0; d >>= 1) {
        s  += __shfl_xor_sync(0xffffffffu, s,  d);
        sq += __shfl_xor_sync(0xffffffffu, sq, d);
    }
    float mean = s * (1.0f/EMB);
    float var  = sq * (1.0f/EMB) - mean*mean;
    float rstd = rsqrtf(var + EPS_LN);

    #pragma unroll
    for (int i = 0; i < 4; i++) {
        float4 sc = *(const float4*)&scale[lane*4 + i*128];
        float4 bb = *(const float4*)&bias [lane*4 + i*128];
        uint4 u;
        u.x = f2tf((v[i].x - mean)*rstd*sc.x + bb.x);
        u.y = f2tf((v[i].y - mean)*rstd*sc.y + bb.y);
        u.z = f2tf((v[i].z - mean)*rstd*sc.z + bb.z);
        u.w = f2tf((v[i].w - mean)*rstd*sc.w + bb.w);
        *(uint4*)&y[lane*4 + i*128] = u;
    }
}

// ---------------- tf32 GEMM 128x128x32, cp.async 3-stage, single barrier ----------------
#define APAD 36
#define WPAD 136
#define STG_WORDS (128*APAD + 32*WPAD)
#define NSTAGE 3
#define GEMM_SMEM_BYTES (NSTAGE*STG_WORDS*4)   // 107520 B

template<bool RELU, bool RES, int TFM>
__device__ __forceinline__ void gemm_core(
    const uint32_t* __restrict__ A,
    const uint32_t* __restrict__ W,
    const float* __restrict__ bias,
    float* __restrict__ C,
    uint32_t* __restrict__ Ctf,
    float tfscale,
    int M, int N, int K, int bx, int by, uint32_t* dsm)
{
    const int tid  = threadIdx.x;
    const int warp = tid >> 5, lane = tid & 31;
    const int m0   = (warp & 1) * 64;
    const int n0   = (warp >> 1) * 32;
    const int group = lane >> 2, tcol = lane & 3;

    const int aRow = tid >> 3;
    const int aCol = (tid & 7) << 2;
    const int wRow = tid >> 3;
    const int wCol = (tid & 7) << 2;

    const uint32_t smb = smem_u32(dsm);
    const uint32_t aDst = smb + (uint32_t)(aRow*APAD + aCol)*4;
    const uint32_t wDst = smb + (uint32_t)(128*APAD + wRow*WPAD + wCol)*4;

    float c[4][4][4];
    #pragma unroll
    for (int mt = 0; mt < 4; mt++)
        #pragma unroll
        for (int nt = 0; nt < 4; nt++)
            #pragma unroll
            for (int j = 0; j < 4; j++) c[mt][nt][j] = 0.f;

    const int ktiles = K >> 5;

    #define ISSUE_STAGE(kt_) do {                                              \
        const int _kb = (kt_) << 5;                                            \
        const uint32_t _so = (uint32_t)(((kt_) % NSTAGE) * STG_WORDS * 4);     \
        _Pragma("unroll")                                                      \
        for (int i = 0; i < 4; i++)                                            \
            CP_ASYNC16(aDst + _so + (uint32_t)(i*32*APAD)*4,                   \
                       &A[(size_t)(by*128 + aRow + i*32)*K + _kb + aCol]);     \
        _Pragma("unroll")                                                      \
        for (int i = 0; i < 4; i++)                                            \
            CP_ASYNC16(wDst + _so + (uint32_t)(i*32)*4,                        \
                       &W[(size_t)(_kb + wRow)*N + bx*128 + wCol + i*32]);     \
    } while (0)

    ISSUE_STAGE(0); CP_COMMIT();
    ISSUE_STAGE(1); CP_COMMIT();

    for (int kt = 0; kt < ktiles; kt++) {
        CP_WAIT1();
        __syncthreads();

        if (kt + 2 < ktiles) ISSUE_STAGE(kt + 2);
        CP_COMMIT();

        const uint32_t* Ass = dsm + (kt % NSTAGE)*STG_WORDS;
        const uint32_t* Wss = Ass + 128*APAD;

        #pragma unroll
        for (int ks = 0; ks < 4; ks++) {
            const int k0 = ks << 3;
            uint32_t af[4][4], bf[4][2];
            #pragma unroll
            for (int mt = 0; mt < 4; mt++) {
                const int mb = m0 + mt*16 + group;
                af[mt][0] = Ass[(mb    )*APAD + k0 + tcol];
                af[mt][1] = Ass[(mb + 8)*APAD + k0 + tcol];
                af[mt][2] = Ass[(mb    )*APAD + k0 + tcol + 4];
                af[mt][3] = Ass[(mb + 8)*APAD + k0 + tcol + 4];
            }
            #pragma unroll
            for (int nt = 0; nt < 4; nt++) {
                const int nb = n0 + nt*8 + group;
                bf[nt][0] = Wss[(k0 + tcol    )*WPAD + nb];
                bf[nt][1] = Wss[(k0 + tcol + 4)*WPAD + nb];
            }
            #pragma unroll
            for (int mt = 0; mt < 4; mt++)
                #pragma unroll
                for (int nt = 0; nt < 4; nt++)
                    mma_tf32(c[mt][nt], af[mt], bf[nt]);
        }
    }
    #undef ISSUE_STAGE

    #pragma unroll
    for (int mt = 0; mt < 4; mt++) {
        #pragma unroll
        for (int nt = 0; nt < 4; nt++) {
            const int col = bx*128 + n0 + nt*8 + tcol*2;
            float2 bb = *(const float2*)&bias[col];
            #pragma unroll
            for (int r = 0; r < 2; r++) {
                const int row = by*128 + m0 + mt*16 + group + r*8;
                float2 v;
                v.x = c[mt][nt][r*2+0] + bb.x;
                v.y = c[mt][nt][r*2+1] + bb.y;
                if (RELU) { v.x = fmaxf(v.x, 0.f); v.y = fmaxf(v.y, 0.f); }
                float2* cp = (float2*)&C[(size_t)row*N + col];
                if (RES) { float2 o = *cp; v.x += o.x; v.y += o.y; }
                if (TFM != 1) *cp = v;
                if (TFM >= 1) {
                    uint2 t2 = { f2tf(v.x * tfscale), f2tf(v.y * tfscale) };
                    *(uint2*)&Ctf[(size_t)row*N + col] = t2;
                }
            }
        }
    }
}

template<bool RELU, bool RES, int TFM>
__global__ __launch_bounds__(256, 2) void gemm128(
    int M, int N, int K,
    const uint32_t* __restrict__ A,
    const uint32_t* __restrict__ W,
    const float* __restrict__ bias,
    float* __restrict__ C,
    uint32_t* __restrict__ Ctf)
{
    extern __shared__ uint32_t dsm[];
    gemm_core<RELU,RES,TFM>(A, W, bias, C, Ctf, 1.0f, M, N, K, blockIdx.x, blockIdx.y, dsm);
}

__global__ __launch_bounds__(256, 2) void qkv_gemm(
    const uint32_t* __restrict__ A,
    const uint32_t* __restrict__ Wq, const uint32_t* __restrict__ Wk, const uint32_t* __restrict__ Wv,
    const float* __restrict__ bq, const float* __restrict__ bk, const float* __restrict__ bv,
    uint32_t* __restrict__ q, uint32_t* __restrict__ k, uint32_t* __restrict__ v)
{
    extern __shared__ uint32_t dsm[];
    const int w   = blockIdx.x >> 2;
    const int nbx = blockIdx.x & 3;
    const uint32_t* W = (w == 0) ? Wq : (w == 1) ? Wk : Wv;
    const float*    b = (w == 0) ? bq : (w == 1) ? bk : bv;
    uint32_t*       C = (w == 0) ? q  : (w == 1) ? k  : v;
    const float    sc = (w == 0) ? 0.125f : 1.0f;
    gemm_core<false,false,1>(A, W, b, nullptr, C, sc, BT, EMB, EMB, nbx, blockIdx.y, dsm);
}

// ---------------- gemm64: 64x128 tile, BK=32, 3-stage ----------------
#define STG64_WORDS (64*APAD + 32*WPAD)        // 6656 words / stage
#define GEMM64_SMEM_BYTES (NSTAGE*STG64_WORDS*4)   // 79872 B

template<bool RELU, bool RES, int TFM>
__global__ __launch_bounds__(256, 2) void gemm64(
    int M, int N, int K,
    const uint32_t* __restrict__ A,
    const uint32_t* __restrict__ W,
    const float* __restrict__ bias,
    float* __restrict__ C,
    uint32_t* __restrict__ Ctf)
{
    extern __shared__ uint32_t dsm[];
    const int bx = blockIdx.x, by = blockIdx.y;
    const int tid  = threadIdx.x;
    const int warp = tid >> 5, lane = tid & 31;
    const int m0   = (warp & 1) * 32;
    const int n0   = (warp >> 1) * 32;
    const int group = lane >> 2, tcol = lane & 3;

    const int aRow = tid >> 3;
    const int aCol = (tid & 7) << 2;
    const int wRow = tid >> 3;
    const int wCol = (tid & 7) << 2;

    const uint32_t smb = smem_u32(dsm);
    const uint32_t aDst = smb + (uint32_t)(aRow*APAD + aCol)*4;
    const uint32_t wDst = smb + (uint32_t)(64*APAD + wRow*WPAD + wCol)*4;

    float c[2][4][4];
    #pragma unroll
    for (int mt = 0; mt < 2; mt++)
        #pragma unroll
        for (int nt = 0; nt < 4; nt++)
            #pragma unroll
            for (int j = 0; j < 4; j++) c[mt][nt][j] = 0.f;

    const int ktiles = K >> 5;

    #define ISSUE64(kt_) do {                                                  \
        const int _kb = (kt_) << 5;                                            \
        const uint32_t _so = (uint32_t)(((kt_) % NSTAGE) * STG64_WORDS * 4);   \
        _Pragma("unroll")                                                      \
        for (int i = 0; i < 2; i++)                                            \
            CP_ASYNC16(aDst + _so + (uint32_t)(i*32*APAD)*4,                   \
                       &A[(size_t)(by*64 + aRow + i*32)*K + _kb + aCol]);      \
        _Pragma("unroll")                                                      \
        for (int i = 0; i < 4; i++)                                            \
            CP_ASYNC16(wDst + _so + (uint32_t)(i*32)*4,                        \
                       &W[(size_t)(_kb + wRow)*N + bx*128 + wCol + i*32]);     \
    } while (0)

    ISSUE64(0); CP_COMMIT();
    ISSUE64(1); CP_COMMIT();

    for (int kt = 0; kt < ktiles; kt++) {
        CP_WAIT1();
        __syncthreads();

        if (kt + 2 < ktiles) ISSUE64(kt + 2);
        CP_COMMIT();

        const uint32_t* Ass = dsm + (kt % NSTAGE)*STG64_WORDS;
        const uint32_t* Wss = Ass + 64*APAD;

        #pragma unroll
        for (int ks = 0; ks < 4; ks++) {
            const int k0 = ks << 3;
            uint32_t af[2][4], bf[4][2];
            #pragma unroll
            for (int mt = 0; mt < 2; mt++) {
                const int mb = m0 + mt*16 + group;
                af[mt][0] = Ass[(mb    )*APAD + k0 + tcol];
                af[mt][1] = Ass[(mb + 8)*APAD + k0 + tcol];
                af[mt][2] = Ass[(mb    )*APAD + k0 + tcol + 4];
                af[mt][3] = Ass[(mb + 8)*APAD + k0 + tcol + 4];
            }
            #pragma unroll
            for (int nt = 0; nt < 4; nt++) {
                const int nb = n0 + nt*8 + group;
                bf[nt][0] = Wss[(k0 + tcol    )*WPAD + nb];
                bf[nt][1] = Wss[(k0 + tcol + 4)*WPAD + nb];
            }
            #pragma unroll
            for (int mt = 0; mt < 2; mt++)
                #pragma unroll
                for (int nt = 0; nt < 4; nt++)
                    mma_tf32(c[mt][nt], af[mt], bf[nt]);
        }
    }
    #undef ISSUE64

    #pragma unroll
    for (int mt = 0; mt < 2; mt++) {
        #pragma unroll
        for (int nt = 0; nt < 4; nt++) {
            const int col = bx*128 + n0 + nt*8 + tcol*2;
            float2 bb = *(const float2*)&bias[col];
            #pragma unroll
            for (int r = 0; r < 2; r++) {
                const int row = by*64 + m0 + mt*16 + group + r*8;
                float2 v;
                v.x = c[mt][nt][r*2+0] + bb.x;
                v.y = c[mt][nt][r*2+1] + bb.y;
                if (RELU) { v.x = fmaxf(v.x, 0.f); v.y = fmaxf(v.y, 0.f); }
                float2* cp = (float2*)&C[(size_t)row*N + col];
                if (RES) { float2 o = *cp; v.x += o.x; v.y += o.y; }
                if (TFM != 1) *cp = v;
                if (TFM >= 1) {
                    uint2 t2 = { f2tf(v.x), f2tf(v.y) };
                    *(uint2*)&Ctf[(size_t)row*N + col] = t2;
                }
            }
        }
    }
}

// ---------------- gemm256: 128x256x32, 1 CTA/SM, for the vocab GEMM ----------------
// 8 warps as 2(M)x4(N); warp tile 64x64 = 4x8 mma tiles; A-frag reuse doubled
// vs gemm128 -> smem read traffic per flop -31%.
#define W2PAD 264   // 256 + 8 (mod32=8 -> bf banks 8tc+g distinct)
#define STG256_WORDS (128*APAD + 32*W2PAD)     // 4608 + 8448 = 13056
#define GEMM256_SMEM_BYTES (NSTAGE*STG256_WORDS*4)  // 156672 B

__global__ __launch_bounds__(256, 1) void gemm256(
    int M, int N, int K,
    const uint32_t* __restrict__ A,
    const uint32_t* __restrict__ W,
    const float* __restrict__ bias,
    float* __restrict__ C)
{
    extern __shared__ uint32_t dsm[];
    const int bx = blockIdx.x, by = blockIdx.y;
    const int tid  = threadIdx.x;
    const int warp = tid >> 5, lane = tid & 31;
    const int m0   = (warp & 1) * 64;
    const int n0   = (warp >> 1) * 64;
    const int group = lane >> 2, tcol = lane & 3;

    const int aRow = tid >> 3;
    const int aCol = (tid & 7) << 2;
    const int wRow = tid >> 3;
    const int wCol = (tid & 7) << 2;

    const uint32_t smb = smem_u32(dsm);
    const uint32_t aDst = smb + (uint32_t)(aRow*APAD + aCol)*4;
    const uint32_t wDst = smb + (uint32_t)(128*APAD + wRow*W2PAD + wCol)*4;

    float c[4][8][4];
    #pragma unroll
    for (int mt = 0; mt < 4; mt++)
        #pragma unroll
        for (int nt = 0; nt < 8; nt++)
            #pragma unroll
            for (int j = 0; j < 4; j++) c[mt][nt][j] = 0.f;

    const int ktiles = K >> 5;

    #define ISSUE256(kt_) do {                                                 \
        const int _kb = (kt_) << 5;                                            \
        const uint32_t _so = (uint32_t)(((kt_) % NSTAGE) * STG256_WORDS * 4);  \
        _Pragma("unroll")                                                      \
        for (int i = 0; i < 4; i++)                                            \
            CP_ASYNC16(aDst + _so + (uint32_t)(i*32*APAD)*4,                   \
                       &A[(size_t)(by*128 + aRow + i*32)*K + _kb + aCol]);     \
        _Pragma("unroll")                                                      \
        for (int i = 0; i < 8; i++)                                            \
            CP_ASYNC16(wDst + _so + (uint32_t)(i*32)*4,                        \
                       &W[(size_t)(_kb + wRow)*N + bx*256 + wCol + i*32]);     \
    } while (0)

    ISSUE256(0); CP_COMMIT();
    ISSUE256(1); CP_COMMIT();

    for (int kt = 0; kt < ktiles; kt++) {
        CP_WAIT1();
        __syncthreads();

        if (kt + 2 < ktiles) ISSUE256(kt + 2);
        CP_COMMIT();

        const uint32_t* Ass = dsm + (kt % NSTAGE)*STG256_WORDS;
        const uint32_t* Wss = Ass + 128*APAD;

        #pragma unroll
        for (int ks = 0; ks < 4; ks++) {
            const int k0 = ks << 3;
            uint32_t af[4][4], bf[8][2];
            #pragma unroll
            for (int mt = 0; mt < 4; mt++) {
                const int mb = m0 + mt*16 + group;
                af[mt][0] = Ass[(mb    )*APAD + k0 + tcol];
                af[mt][1] = Ass[(mb + 8)*APAD + k0 + tcol];
                af[mt][2] = Ass[(mb    )*APAD + k0 + tcol + 4];
                af[mt][3] = Ass[(mb + 8)*APAD + k0 + tcol + 4];
            }
            #pragma unroll
            for (int nt = 0; nt < 8; nt++) {
                const int nb = n0 + nt*8 + group;
                bf[nt][0] = Wss[(k0 + tcol    )*W2PAD + nb];
                bf[nt][1] = Wss[(k0 + tcol + 4)*W2PAD + nb];
            }
            #pragma unroll
            for (int mt = 0; mt < 4; mt++)
                #pragma unroll
                for (int nt = 0; nt < 8; nt++)
                    mma_tf32(c[mt][nt], af[mt], bf[nt]);
        }
    }
    #undef ISSUE256

    #pragma unroll
    for (int mt = 0; mt < 4; mt++) {
        #pragma unroll
        for (int nt = 0; nt < 8; nt++) {
            const int col = bx*256 + n0 + nt*8 + tcol*2;
            float2 bb = *(const float2*)&bias[col];
            #pragma unroll
            for (int r = 0; r < 2; r++) {
                const int row = by*128 + m0 + mt*16 + group + r*8;
                float2 v;
                v.x = c[mt][nt][r*2+0] + bb.x;
                v.y = c[mt][nt][r*2+1] + bb.y;
                *(float2*)&C[(size_t)row*N + col] = v;
            }
        }
    }
}

// ---------------- flash attention: diagonal-paired 64-query tiles (unchanged) ----------------
#define QS_STRIDE 68
#define KS_STRIDE 68
#define VS_STRIDE 72
#define PS_STRIDE 68
#define KV_WORDS  (64*KS_STRIDE + 64*VS_STRIDE)
#define ATT_SMEM_WORDS (64*QS_STRIDE + 2*KV_WORDS)
#define ATT_SMEM_BYTES (ATT_SMEM_WORDS*4)          // 89088 B -> 2 CTAs/SM

#define NQT (SEQ/64)

__global__ __launch_bounds__(128, 2) void attn_mma_kernel(
        const uint32_t* __restrict__ Q,
        const uint32_t* __restrict__ K,
        const uint32_t* __restrict__ V,
        uint32_t* __restrict__ O)
{
    extern __shared__ uint32_t smw[];
    uint32_t* qs  = smw;
    uint32_t* kv0 = qs + 64*QS_STRIDE;
    uint32_t* ps  = qs;

    const int pair = blockIdx.x, hh = blockIdx.y, bb = blockIdx.z;
    const int tid = threadIdx.x, warp = tid >> 5, lane = tid & 31;
    const int g = lane >> 2, tc = lane & 3;
    const int wq = warp * 16;

    const size_t base = ((size_t)bb*SEQ)*EMB + (size_t)hh*HEADD;
    const uint32_t kvb = smem_u32(kv0);

    const int tok0 = tid >> 4;
    const int d4s  = (tid & 15) << 2;

    #define ATT_ISSUE(kt_) do {                                                     \
        const uint32_t _so = (uint32_t)(((kt_) & 1) * KV_WORDS * 4);                \
        _Pragma("unroll")                                                           \
        for (int i = 0; i < 8; i++) {                                               \
            int _tok = tok0 + i*8;                                                  \
            CP_ASYNC16(kvb + _so + (uint32_t)(_tok*KS_STRIDE + d4s)*4,              \
                       &K[base + (size_t)((kt_)*64 + _tok)*EMB + d4s]);             \
            CP_ASYNC16(kvb + _so + (uint32_t)(64*KS_STRIDE + _tok*VS_STRIDE + d4s)*4,\
                       &V[base + (size_t)((kt_)*64 + _tok)*EMB + d4s]);             \
        }                                                                           \
    } while (0)

    for (int phase = 0; phase < 2; phase++) {
        const int qt  = phase ? (NQT - 1 - pair) : pair;
        const int nkt = qt + 1;

        #pragma unroll
        for (int i = 0; i < 8; i++) {
            int f   = i*128 + tid;
            int row = f >> 4, d4 = (f & 15) << 2;
            *(uint4*)&qs[row*QS_STRIDE + d4] =
                *(const uint4*)&Q[base + (size_t)(qt*64 + row)*EMB + d4];
        }
        ATT_ISSUE(0); CP_COMMIT();
        __syncthreads();

        uint32_t qf[8][4];
        #pragma unroll
        for (int ki = 0; ki < 8; ki++) {
            int k0 = ki*8;
            qf[ki][0] = qs[(wq+g  )*QS_STRIDE + k0 + tc];
            qf[ki][1] = qs[(wq+g+8)*QS_STRIDE + k0 + tc];
            qf[ki][2] = qs[(wq+g  )*QS_STRIDE + k0 + tc + 4];
            qf[ki][3] = qs[(wq+g+8)*QS_STRIDE + k0 + tc + 4];
        }

        float o[8][4];
        #pragma unroll
        for (int nt = 0; nt < 8; nt++)
            #pragma unroll
            for (int j = 0; j < 4; j++) o[nt][j] = 0.f;
        float m0 = -1e30f, m1 = -1e30f, l0 = 0.f, l1 = 0.f;

        for (int kt = 0; kt < nkt; kt++) {
            if (kt + 1 < nkt) { ATT_ISSUE(kt + 1); CP_COMMIT(); CP_WAIT1(); }
            else              { CP_WAIT0(); }
            __syncthreads();

            const uint32_t* ks = kv0 + (kt & 1)*KV_WORDS;
            const uint32_t* vs = ks + 64*KS_STRIDE;

            float sc[8][4];
            #pragma unroll
            for (int nt = 0; nt < 8; nt++)
                #pragma unroll
                for (int j = 0; j < 4; j++) sc[nt][j] = 0.f;

            #pragma unroll
            for (int ki = 0; ki < 8; ki++) {
                int k0 = ki*8;
                uint32_t bf[8][2];
                #pragma unroll
                for (int nt = 0; nt < 8; nt++) {
                    int nb = nt*8 + g;
                    bf[nt][0] = ks[nb*KS_STRIDE + k0 + tc];
                    bf[nt][1] = ks[nb*KS_STRIDE + k0 + tc + 4];
                }
                #pragma unroll
                for (int nt = 0; nt < 8; nt++)
                    mma_tf32(sc[nt], qf[ki], bf[nt]);
            }

            if (kt >= qt) {
                const int row0 = qt*64 + wq + g;
                #pragma unroll
                for (int nt = 0; nt < 8; nt++) {
                    int c0 = kt*64 + nt*8 + 2*tc;
                    if (c0     > row0    ) sc[nt][0] = -1e30f;
                    if (c0 + 1 > row0    ) sc[nt][1] = -1e30f;
                    if (c0     > row0 + 8) sc[nt][2] = -1e30f;
                    if (c0 + 1 > row0 + 8) sc[nt][3] = -1e30f;
                }
            }

            float r0 = -1e30f, r1 = -1e30f;
            #pragma unroll
            for (int nt = 0; nt < 8; nt++) {
                r0 = fmaxf(r0, fmaxf(sc[nt][0], sc[nt][1]));
                r1 = fmaxf(r1, fmaxf(sc[nt][2], sc[nt][3]));
            }
            r0 = fmaxf(r0, __shfl_xor_sync(0xffffffffu, r0, 1));
            r0 = fmaxf(r0, __shfl_xor_sync(0xffffffffu, r0, 2));
            r1 = fmaxf(r1, __shfl_xor_sync(0xffffffffu, r1, 1));
            r1 = fmaxf(r1, __shfl_xor_sync(0xffffffffu, r1, 2));

            float mn0 = fmaxf(m0, r0), mn1 = fmaxf(m1, r1);
            float cor0 = __expf(m0 - mn0), cor1 = __expf(m1 - mn1);
            m0 = mn0; m1 = mn1;
            l0 *= cor0; l1 *= cor1;
            #pragma unroll
            for (int nt = 0; nt < 8; nt++) {
                o[nt][0] *= cor0; o[nt][1] *= cor0;
                o[nt][2] *= cor1; o[nt][3] *= cor1;
            }

            float s0 = 0.f, s1 = 0.f;
            #pragma unroll
            for (int nt = 0; nt < 8; nt++) {
                float p00 = __expf(sc[nt][0] - mn0);
                float p01 = __expf(sc[nt][1] - mn0);
                float p10 = __expf(sc[nt][2] - mn1);
                float p11 = __expf(sc[nt][3] - mn1);
                s0 += p00 + p01; s1 += p10 + p11;
                int col = nt*8 + 2*tc;
                ps[(wq+g  )*PS_STRIDE + col    ] = f2tf(p00);
                ps[(wq+g  )*PS_STRIDE + col + 1] = f2tf(p01);
                ps[(wq+g+8)*PS_STRIDE + col    ] = f2tf(p10);
                ps[(wq+g+8)*PS_STRIDE + col + 1] = f2tf(p11);
            }
            s0 += __shfl_xor_sync(0xffffffffu, s0, 1);
            s0 += __shfl_xor_sync(0xffffffffu, s0, 2);
            s1 += __shfl_xor_sync(0xffffffffu, s1, 1);
            s1 += __shfl_xor_sync(0xffffffffu, s1, 2);
            l0 += s0; l1 += s1;
            __syncwarp();

            #pragma unroll
            for (int ki = 0; ki < 8; ki++) {
                int k0 = ki*8;
                uint32_t af[4];
                af[0] = ps[(wq+g  )*PS_STRIDE + k0 + tc];
                af[1] = ps[(wq+g+8)*PS_STRIDE + k0 + tc];
                af[2] = ps[(wq+g  )*PS_STRIDE + k0 + tc + 4];
                af[3] = ps[(wq+g+8)*PS_STRIDE + k0 + tc + 4];
                uint32_t bf[8][2];
                #pragma unroll
                for (int nt = 0; nt < 8; nt++) {
                    int nb = nt*8 + g;
                    bf[nt][0] = vs[(k0 + tc    )*VS_STRIDE + nb];
                    bf[nt][1] = vs[(k0 + tc + 4)*VS_STRIDE + nb];
                }
                #pragma unroll
                for (int nt = 0; nt < 8; nt++)
                    mma_tf32(o[nt], af, bf[nt]);
            }
            __syncthreads();
        }

        float inv0 = 1.0f / l0, inv1 = 1.0f / l1;
        const int row0 = qt*64 + wq + g;
        #pragma unroll
        for (int nt = 0; nt < 8; nt++) {
            int d = nt*8 + 2*tc;
            uint2 a = { f2tf(o[nt][0]*inv0), f2tf(o[nt][1]*inv0) };
            *(uint2*)&O[base + (size_t)row0*EMB + d] = a;
            uint2 b = { f2tf(o[nt][2]*inv1), f2tf(o[nt][3]*inv1) };
            *(uint2*)&O[base + (size_t)(row0+8)*EMB + d] = b;
        }
    }
    #undef ATT_ISSUE
}

// ---------------- orchestration ----------------
extern "C" void kernel_launch(void* const* d_in, const int* in_sizes, int n_in,
                              void* d_out, int out_size)
{
    (void)in_sizes; (void)n_in;
    const int*   x       = (const int*)  d_in[0];
    const float* tok_emb = (const float*)d_in[1];
    const float* pos_emb = (const float*)d_in[2];
    const float* Wq   = (const float*)d_in[3];
    const float* bq   = (const float*)d_in[4];
    const float* Wk   = (const float*)d_in[5];
    const float* bk   = (const float*)d_in[6];
    const float* Wv   = (const float*)d_in[7];
    const float* bv   = (const float*)d_in[8];
    const float* Wo   = (const float*)d_in[9];
    const float* bo   = (const float*)d_in[10];
    const float* ln1s = (const float*)d_in[11];
    const float* ln1b = (const float*)d_in[12];
    const float* ln2s = (const float*)d_in[13];
    const float* ln2b = (const float*)d_in[14];
    const float* W1   = (const float*)d_in[15];
    const float* b1   = (const float*)d_in[16];
    const float* W2   = (const float*)d_in[17];
    const float* b2   = (const float*)d_in[18];
    const float* Wout = (const float*)d_in[19];
    const float* bout = (const float*)d_in[20];
    float* out = (float*)d_out;
    (void)out_size;

    float *h; uint32_t *y, *q, *k, *v, *o, *ff, *htf, *wtf;
    cudaGetSymbolAddress((void**)&h,   g_h);
    cudaGetSymbolAddress((void**)&y,   g_y);
    cudaGetSymbolAddress((void**)&q,   g_q);
    cudaGetSymbolAddress((void**)&k,   g_k);
    cudaGetSymbolAddress((void**)&v,   g_v);
    cudaGetSymbolAddress((void**)&o,   g_o);
    cudaGetSymbolAddress((void**)&ff,  g_ff);
    cudaGetSymbolAddress((void**)&htf, g_htf);
    cudaGetSymbolAddress((void**)&wtf, g_wtf);

    cudaFuncSetAttribute(gemm128<false,false,0>,
        cudaFuncAttributeMaxDynamicSharedMemorySize, GEMM_SMEM_BYTES);
    cudaFuncSetAttribute(gemm128<true,false,1>,
        cudaFuncAttributeMaxDynamicSharedMemorySize, GEMM_SMEM_BYTES);
    cudaFuncSetAttribute(qkv_gemm,
        cudaFuncAttributeMaxDynamicSharedMemorySize, GEMM_SMEM_BYTES);
    cudaFuncSetAttribute(gemm64<false,true,0>,
        cudaFuncAttributeMaxDynamicSharedMemorySize, GEMM64_SMEM_BYTES);
    cudaFuncSetAttribute(gemm64<false,true,1>,
        cudaFuncAttributeMaxDynamicSharedMemorySize, GEMM64_SMEM_BYTES);
    cudaFuncSetAttribute(gemm256,
        cudaFuncAttributeMaxDynamicSharedMemorySize, GEMM256_SMEM_BYTES);
    cudaFuncSetAttribute(attn_mma_kernel,
        cudaFuncAttributeMaxDynamicSharedMemorySize, ATT_SMEM_BYTES);

    // launch 1: fused weight conversion + embedding
    prep_kernel<<<EMBED_BLOCKS + CVT_BLOCKS, 256>>>(
        Wq, Wk, Wv, Wo, W1, W2, Wout, wtf, x, tok_emb, pos_emb, h);

    const int M = BT;

    for (int i = 0; i < NLAYER; i++) {
        const uint32_t* Wqi = wtf + OFF_WQ + (size_t)i*EMB*EMB;
        const uint32_t* Wki = wtf + OFF_WK + (size_t)i*EMB*EMB;
        const uint32_t* Wvi = wtf + OFF_WV + (size_t)i*EMB*EMB;
        const uint32_t* Woi = wtf + OFF_WO + (size_t)i*EMB*EMB;
        const uint32_t* W1i = wtf + OFF_W1 + (size_t)i*EMB*FFDIM;
        const uint32_t* W2i = wtf + OFF_W2 + (size_t)i*FFDIM*EMB;

        ln_kernel<<<BT/8, 256>>>(h, ln1s + i*EMB, ln1b + i*EMB, y);

        qkv_gemm<<<dim3(12, M/128), 256, GEMM_SMEM_BYTES>>>(
            y, Wqi, Wki, Wvi, bq + i*EMB, bk + i*EMB, bv + i*EMB, q, k, v);

        attn_mma_kernel<<<dim3(NQT/2, NHEAD, BATCH), 128, ATT_SMEM_BYTES>>>(q, k, v, o);

        gemm64<false,true,0><<<dim3(EMB/128, M/64), 256, GEMM64_SMEM_BYTES>>>(
            M, EMB, EMB, o, Woi, bo + i*EMB, h, nullptr);

        ln_kernel<<<BT/8, 256>>>(h, ln2s + i*EMB, ln2b + i*EMB, y);

        gemm128<true,false,1><<<dim3(FFDIM/128, M/128), 256, GEMM_SMEM_BYTES>>>(
            M, FFDIM, EMB, y, W1i, b1 + i*FFDIM, nullptr, ff);

        if (i < NLAYER - 1) {
            gemm64<false,true,0><<<dim3(EMB/128, M/64), 256, GEMM64_SMEM_BYTES>>>(
                M, EMB, FFDIM, ff, W2i, b2 + i*EMB, h, nullptr);
        } else {
            gemm64<false,true,1><<<dim3(EMB/128, M/64), 256, GEMM64_SMEM_BYTES>>>(
                M, EMB, FFDIM, ff, W2i, b2 + i*EMB, h, htf);
        }
    }

    gemm256<<<dim3(VOCAB/256, M/128), 256, GEMM256_SMEM_BYTES>>>(
        M, VOCAB, EMB, htf, wtf + OFF_WOUT, bout, out);
}

// round 17
// speedup vs baseline: 1.0236x; 1.0236x over previous
#include <cuda_runtime.h>
#include <cuda_bf16.h>
#include <math.h>
#include <stdint.h>

// ---------------- problem constants ----------------
#define VOCAB 32000
#define EMB   512
#define SEQ   2048
#define NHEAD 8
#define NLAYER 6
#define FFDIM 2048
#define BATCH 2
#define HEADD 64
#define BT    (BATCH*SEQ)      // 4096 tokens
#define EPS_LN 1e-5f

// ---------------- scratch (device globals; no allocation allowed) ----------------
__device__ float    g_h  [BT*EMB];     // residual stream (fp32)
__device__ uint32_t g_y  [BT*EMB];     // LN output (tf32)
__device__ uint32_t g_q  [BT*EMB];     // tf32, pre-scaled by 0.125
__device__ uint32_t g_k  [BT*EMB];     // tf32
__device__ uint32_t g_v  [BT*EMB];     // tf32
__device__ uint32_t g_o  [BT*EMB];     // attention output (tf32)
__device__ uint32_t g_ff [BT*FFDIM];   // FFN hidden (tf32)
__device__ uint32_t g_htf[BT*EMB];     // final residual (tf32) for vocab gemm

// tf32 weight mirror, same [K][N] layout as inputs
#define EE6 (NLAYER*EMB*EMB)
#define EF6 (NLAYER*EMB*FFDIM)
#define OFF_WQ   0
#define OFF_WK   (EE6)
#define OFF_WV   (2*EE6)
#define OFF_WO   (3*EE6)
#define OFF_W1   (4*EE6)
#define OFF_W2   (4*EE6 + EF6)
#define OFF_WOUT (4*EE6 + 2*EF6)
#define WTF_TOTAL (4*EE6 + 2*EF6 + EMB*VOCAB)
__device__ uint32_t g_wtf[WTF_TOTAL];

#define EMBED_BLOCKS 2048
#define CVT_BLOCKS   (WTF_TOTAL/1024)

// ---------------- helpers ----------------
__device__ __forceinline__ uint32_t f2tf(float f) {
    uint32_t u; asm("cvt.rna.tf32.f32 %0, %1;" : "=r"(u) : "f"(f)); return u;
}
__device__ __forceinline__ void mma_tf32(float* c, const uint32_t* a, const uint32_t* b) {
    asm volatile(
        "mma.sync.aligned.m16n8k8.row.col.f32.tf32.tf32.f32 "
        "{%0,%1,%2,%3}, {%4,%5,%6,%7}, {%8,%9}, {%0,%1,%2,%3};\n"
        : "+f"(c[0]), "+f"(c[1]), "+f"(c[2]), "+f"(c[3])
        : "r"(a[0]), "r"(a[1]), "r"(a[2]), "r"(a[3]),
          "r"(b[0]), "r"(b[1]));
}
__device__ __forceinline__ uint32_t smem_u32(const void* p) {
    uint32_t a;
    asm("{ .reg .u64 t; cvta.to.shared.u64 t, %1; cvt.u32.u64 %0, t; }" : "=r"(a) : "l"(p));
    return a;
}
#define CP_ASYNC16(dst, src) \
    asm volatile("cp.async.cg.shared.global [%0], [%1], 16;" :: "r"(dst), "l"(src))
#define CP_COMMIT() asm volatile("cp.async.commit_group;" ::: "memory")
#define CP_WAIT1()  asm volatile("cp.async.wait_group 1;" ::: "memory")
#define CP_WAIT0()  asm volatile("cp.async.wait_group 0;" ::: "memory")

// ---------------- fused prep: weight convert + embedding ----------------
__global__ void prep_kernel(
    const float* __restrict__ Wq, const float* __restrict__ Wk,
    const float* __restrict__ Wv, const float* __restrict__ Wo,
    const float* __restrict__ W1, const float* __restrict__ W2,
    const float* __restrict__ Wout, uint32_t* __restrict__ d,
    const int* __restrict__ x, const float* __restrict__ tok,
    const float* __restrict__ pos, float* __restrict__ h)
{
    if (blockIdx.x < EMBED_BLOCKS) {
        size_t i = ((size_t)blockIdx.x * 256 + threadIdx.x) * 4;
        int row = (int)(i >> 9);
        int col = (int)(i & 511);
        int t   = row % SEQ;
        int id  = x[row];
        float4 a = *(const float4*)&tok[(size_t)id * EMB + col];
        float4 b = *(const float4*)&pos[(size_t)t  * EMB + col];
        float4 r = { a.x + b.x, a.y + b.y, a.z + b.z, a.w + b.w };
        *(float4*)&h[i] = r;
        return;
    }
    size_t i = ((size_t)(blockIdx.x - EMBED_BLOCKS) * 256 + threadIdx.x) * 4;
    if (i >= WTF_TOTAL) return;
    const float* s; size_t loc;
    if      (i < OFF_WK)   { s = Wq;   loc = i;            }
    else if (i < OFF_WV)   { s = Wk;   loc = i - OFF_WK;   }
    else if (i < OFF_WO)   { s = Wv;   loc = i - OFF_WV;   }
    else if (i < OFF_W1)   { s = Wo;   loc = i - OFF_WO;   }
    else if (i < OFF_W2)   { s = W1;   loc = i - OFF_W1;   }
    else if (i < OFF_WOUT) { s = W2;   loc = i - OFF_W2;   }
    else                   { s = Wout; loc = i - OFF_WOUT; }
    float4 v = *(const float4*)&s[loc];
    uint4 u = { f2tf(v.x), f2tf(v.y), f2tf(v.z), f2tf(v.w) };
    *(uint4*)&d[i] = u;
}

// ---------------- layernorm: one warp per row, shuffle-only ----------------
__global__ __launch_bounds__(256) void ln_kernel(
    const float* __restrict__ X,
    const float* __restrict__ scale,
    const float* __restrict__ bias,
    uint32_t* __restrict__ Y)
{
    const int warp = threadIdx.x >> 5, lane = threadIdx.x & 31;
    const int row  = blockIdx.x * 8 + warp;
    const float* x = X + (size_t)row * EMB;
    uint32_t*    y = Y + (size_t)row * EMB;

    float4 v[4];
    float s = 0.f, sq = 0.f;
    #pragma unroll
    for (int i = 0; i < 4; i++) {
        v[i] = *(const float4*)&x[lane*4 + i*128];
        s  += v[i].x + v[i].y + v[i].z + v[i].w;
        sq += v[i].x*v[i].x + v[i].y*v[i].y + v[i].z*v[i].z + v[i].w*v[i].w;
    }
    #pragma unroll
    for (int d = 16; d > 0; d >>= 1) {
        s  += __shfl_xor_sync(0xffffffffu, s,  d);
        sq += __shfl_xor_sync(0xffffffffu, sq, d);
    }
    float mean = s * (1.0f/EMB);
    float var  = sq * (1.0f/EMB) - mean*mean;
    float rstd = rsqrtf(var + EPS_LN);

    #pragma unroll
    for (int i = 0; i < 4; i++) {
        float4 sc = *(const float4*)&scale[lane*4 + i*128];
        float4 bb = *(const float4*)&bias [lane*4 + i*128];
        uint4 u;
        u.x = f2tf((v[i].x - mean)*rstd*sc.x + bb.x);
        u.y = f2tf((v[i].y - mean)*rstd*sc.y + bb.y);
        u.z = f2tf((v[i].z - mean)*rstd*sc.z + bb.z);
        u.w = f2tf((v[i].w - mean)*rstd*sc.w + bb.w);
        *(uint4*)&y[lane*4 + i*128] = u;
    }
}

// ---------------- tf32 GEMM 128x128x32, cp.async 3-stage, single barrier ----------------
#define APAD 36
#define WPAD 136
#define STG_WORDS (128*APAD + 32*WPAD)
#define NSTAGE 3
#define GEMM_SMEM_BYTES (NSTAGE*STG_WORDS*4)   // 107520 B

template<bool RELU, bool RES, int TFM>
__device__ __forceinline__ void gemm_core(
    const uint32_t* __restrict__ A,
    const uint32_t* __restrict__ W,
    const float* __restrict__ bias,
    float* __restrict__ C,
    uint32_t* __restrict__ Ctf,
    float tfscale,
    int M, int N, int K, int bx, int by, uint32_t* dsm)
{
    const int tid  = threadIdx.x;
    const int warp = tid >> 5, lane = tid & 31;
    const int m0   = (warp & 1) * 64;
    const int n0   = (warp >> 1) * 32;
    const int group = lane >> 2, tcol = lane & 3;

    const int aRow = tid >> 3;
    const int aCol = (tid & 7) << 2;
    const int wRow = tid >> 3;
    const int wCol = (tid & 7) << 2;

    const uint32_t smb = smem_u32(dsm);
    const uint32_t aDst = smb + (uint32_t)(aRow*APAD + aCol)*4;
    const uint32_t wDst = smb + (uint32_t)(128*APAD + wRow*WPAD + wCol)*4;

    float c[4][4][4];
    #pragma unroll
    for (int mt = 0; mt < 4; mt++)
        #pragma unroll
        for (int nt = 0; nt < 4; nt++)
            #pragma unroll
            for (int j = 0; j < 4; j++) c[mt][nt][j] = 0.f;

    const int ktiles = K >> 5;

    #define ISSUE_STAGE(kt_) do {                                              \
        const int _kb = (kt_) << 5;                                            \
        const uint32_t _so = (uint32_t)(((kt_) % NSTAGE) * STG_WORDS * 4);     \
        _Pragma("unroll")                                                      \
        for (int i = 0; i < 4; i++)                                            \
            CP_ASYNC16(aDst + _so + (uint32_t)(i*32*APAD)*4,                   \
                       &A[(size_t)(by*128 + aRow + i*32)*K + _kb + aCol]);     \
        _Pragma("unroll")                                                      \
        for (int i = 0; i < 4; i++)                                            \
            CP_ASYNC16(wDst + _so + (uint32_t)(i*32)*4,                        \
                       &W[(size_t)(_kb + wRow)*N + bx*128 + wCol + i*32]);     \
    } while (0)

    ISSUE_STAGE(0); CP_COMMIT();
    ISSUE_STAGE(1); CP_COMMIT();

    for (int kt = 0; kt < ktiles; kt++) {
        CP_WAIT1();
        __syncthreads();

        if (kt + 2 < ktiles) ISSUE_STAGE(kt + 2);
        CP_COMMIT();

        const uint32_t* Ass = dsm + (kt % NSTAGE)*STG_WORDS;
        const uint32_t* Wss = Ass + 128*APAD;

        #pragma unroll
        for (int ks = 0; ks < 4; ks++) {
            const int k0 = ks << 3;
            uint32_t af[4][4], bf[4][2];
            #pragma unroll
            for (int mt = 0; mt < 4; mt++) {
                const int mb = m0 + mt*16 + group;
                af[mt][0] = Ass[(mb    )*APAD + k0 + tcol];
                af[mt][1] = Ass[(mb + 8)*APAD + k0 + tcol];
                af[mt][2] = Ass[(mb    )*APAD + k0 + tcol + 4];
                af[mt][3] = Ass[(mb + 8)*APAD + k0 + tcol + 4];
            }
            #pragma unroll
            for (int nt = 0; nt < 4; nt++) {
                const int nb = n0 + nt*8 + group;
                bf[nt][0] = Wss[(k0 + tcol    )*WPAD + nb];
                bf[nt][1] = Wss[(k0 + tcol + 4)*WPAD + nb];
            }
            #pragma unroll
            for (int mt = 0; mt < 4; mt++)
                #pragma unroll
                for (int nt = 0; nt < 4; nt++)
                    mma_tf32(c[mt][nt], af[mt], bf[nt]);
        }
    }
    #undef ISSUE_STAGE

    #pragma unroll
    for (int mt = 0; mt < 4; mt++) {
        #pragma unroll
        for (int nt = 0; nt < 4; nt++) {
            const int col = bx*128 + n0 + nt*8 + tcol*2;
            float2 bb = *(const float2*)&bias[col];
            #pragma unroll
            for (int r = 0; r < 2; r++) {
                const int row = by*128 + m0 + mt*16 + group + r*8;
                float2 v;
                v.x = c[mt][nt][r*2+0] + bb.x;
                v.y = c[mt][nt][r*2+1] + bb.y;
                if (RELU) { v.x = fmaxf(v.x, 0.f); v.y = fmaxf(v.y, 0.f); }
                float2* cp = (float2*)&C[(size_t)row*N + col];
                if (RES) { float2 o = *cp; v.x += o.x; v.y += o.y; }
                if (TFM != 1) *cp = v;
                if (TFM >= 1) {
                    uint2 t2 = { f2tf(v.x * tfscale), f2tf(v.y * tfscale) };
                    *(uint2*)&Ctf[(size_t)row*N + col] = t2;
                }
            }
        }
    }
}

template<bool RELU, bool RES, int TFM>
__global__ __launch_bounds__(256, 2) void gemm128(
    int M, int N, int K,
    const uint32_t* __restrict__ A,
    const uint32_t* __restrict__ W,
    const float* __restrict__ bias,
    float* __restrict__ C,
    uint32_t* __restrict__ Ctf)
{
    extern __shared__ uint32_t dsm[];
    gemm_core<RELU,RES,TFM>(A, W, bias, C, Ctf, 1.0f, M, N, K, blockIdx.x, blockIdx.y, dsm);
}

__global__ __launch_bounds__(256, 2) void qkv_gemm(
    const uint32_t* __restrict__ A,
    const uint32_t* __restrict__ Wq, const uint32_t* __restrict__ Wk, const uint32_t* __restrict__ Wv,
    const float* __restrict__ bq, const float* __restrict__ bk, const float* __restrict__ bv,
    uint32_t* __restrict__ q, uint32_t* __restrict__ k, uint32_t* __restrict__ v)
{
    extern __shared__ uint32_t dsm[];
    const int w   = blockIdx.x >> 2;
    const int nbx = blockIdx.x & 3;
    const uint32_t* W = (w == 0) ? Wq : (w == 1) ? Wk : Wv;
    const float*    b = (w == 0) ? bq : (w == 1) ? bk : bv;
    uint32_t*       C = (w == 0) ? q  : (w == 1) ? k  : v;
    const float    sc = (w == 0) ? 0.125f : 1.0f;
    gemm_core<false,false,1>(A, W, b, nullptr, C, sc, BT, EMB, EMB, nbx, blockIdx.y, dsm);
}

// ---------------- gemm64: 64x128 tile, BK=32, 3-stage ----------------
#define STG64_WORDS (64*APAD + 32*WPAD)        // 6656 words / stage
#define GEMM64_SMEM_BYTES (NSTAGE*STG64_WORDS*4)   // 79872 B

template<bool RELU, bool RES, int TFM>
__global__ __launch_bounds__(256, 2) void gemm64(
    int M, int N, int K,
    const uint32_t* __restrict__ A,
    const uint32_t* __restrict__ W,
    const float* __restrict__ bias,
    float* __restrict__ C,
    uint32_t* __restrict__ Ctf)
{
    extern __shared__ uint32_t dsm[];
    const int bx = blockIdx.x, by = blockIdx.y;
    const int tid  = threadIdx.x;
    const int warp = tid >> 5, lane = tid & 31;
    const int m0   = (warp & 1) * 32;
    const int n0   = (warp >> 1) * 32;
    const int group = lane >> 2, tcol = lane & 3;

    const int aRow = tid >> 3;
    const int aCol = (tid & 7) << 2;
    const int wRow = tid >> 3;
    const int wCol = (tid & 7) << 2;

    const uint32_t smb = smem_u32(dsm);
    const uint32_t aDst = smb + (uint32_t)(aRow*APAD + aCol)*4;
    const uint32_t wDst = smb + (uint32_t)(64*APAD + wRow*WPAD + wCol)*4;

    float c[2][4][4];
    #pragma unroll
    for (int mt = 0; mt < 2; mt++)
        #pragma unroll
        for (int nt = 0; nt < 4; nt++)
            #pragma unroll
            for (int j = 0; j < 4; j++) c[mt][nt][j] = 0.f;

    const int ktiles = K >> 5;

    #define ISSUE64(kt_) do {                                                  \
        const int _kb = (kt_) << 5;                                            \
        const uint32_t _so = (uint32_t)(((kt_) % NSTAGE) * STG64_WORDS * 4);   \
        _Pragma("unroll")                                                      \
        for (int i = 0; i < 2; i++)                                            \
            CP_ASYNC16(aDst + _so + (uint32_t)(i*32*APAD)*4,                   \
                       &A[(size_t)(by*64 + aRow + i*32)*K + _kb + aCol]);      \
        _Pragma("unroll")                                                      \
        for (int i = 0; i < 4; i++)                                            \
            CP_ASYNC16(wDst + _so + (uint32_t)(i*32)*4,                        \
                       &W[(size_t)(_kb + wRow)*N + bx*128 + wCol + i*32]);     \
    } while (0)

    ISSUE64(0); CP_COMMIT();
    ISSUE64(1); CP_COMMIT();

    for (int kt = 0; kt < ktiles; kt++) {
        CP_WAIT1();
        __syncthreads();

        if (kt + 2 < ktiles) ISSUE64(kt + 2);
        CP_COMMIT();

        const uint32_t* Ass = dsm + (kt % NSTAGE)*STG64_WORDS;
        const uint32_t* Wss = Ass + 64*APAD;

        #pragma unroll
        for (int ks = 0; ks < 4; ks++) {
            const int k0 = ks << 3;
            uint32_t af[2][4], bf[4][2];
            #pragma unroll
            for (int mt = 0; mt < 2; mt++) {
                const int mb = m0 + mt*16 + group;
                af[mt][0] = Ass[(mb    )*APAD + k0 + tcol];
                af[mt][1] = Ass[(mb + 8)*APAD + k0 + tcol];
                af[mt][2] = Ass[(mb    )*APAD + k0 + tcol + 4];
                af[mt][3] = Ass[(mb + 8)*APAD + k0 + tcol + 4];
            }
            #pragma unroll
            for (int nt = 0; nt < 4; nt++) {
                const int nb = n0 + nt*8 + group;
                bf[nt][0] = Wss[(k0 + tcol    )*WPAD + nb];
                bf[nt][1] = Wss[(k0 + tcol + 4)*WPAD + nb];
            }
            #pragma unroll
            for (int mt = 0; mt < 2; mt++)
                #pragma unroll
                for (int nt = 0; nt < 4; nt++)
                    mma_tf32(c[mt][nt], af[mt], bf[nt]);
        }
    }
    #undef ISSUE64

    #pragma unroll
    for (int mt = 0; mt < 2; mt++) {
        #pragma unroll
        for (int nt = 0; nt < 4; nt++) {
            const int col = bx*128 + n0 + nt*8 + tcol*2;
            float2 bb = *(const float2*)&bias[col];
            #pragma unroll
            for (int r = 0; r < 2; r++) {
                const int row = by*64 + m0 + mt*16 + group + r*8;
                float2 v;
                v.x = c[mt][nt][r*2+0] + bb.x;
                v.y = c[mt][nt][r*2+1] + bb.y;
                if (RELU) { v.x = fmaxf(v.x, 0.f); v.y = fmaxf(v.y, 0.f); }
                float2* cp = (float2*)&C[(size_t)row*N + col];
                if (RES) { float2 o = *cp; v.x += o.x; v.y += o.y; }
                if (TFM != 1) *cp = v;
                if (TFM >= 1) {
                    uint2 t2 = { f2tf(v.x), f2tf(v.y) };
                    *(uint2*)&Ctf[(size_t)row*N + col] = t2;
                }
            }
        }
    }
}

// ---------------- flash attention: unpaired 64-query tiles, LPT order ----------------
// Grid 512 flat: idx>>4 = qt rank (longest first), idx&15 = (bb<<3)|hh.
// Work-stealing backfills freed slots with progressively shorter tasks.
#define QS_STRIDE 68
#define KS_STRIDE 68
#define VS_STRIDE 72
#define PS_STRIDE 68
#define KV_WORDS  (64*KS_STRIDE + 64*VS_STRIDE)
#define ATT_SMEM_WORDS (64*QS_STRIDE + 2*KV_WORDS)
#define ATT_SMEM_BYTES (ATT_SMEM_WORDS*4)          // 89088 B -> 2 CTAs/SM

#define NQT (SEQ/64)

__global__ __launch_bounds__(128, 2) void attn_mma_kernel(
        const uint32_t* __restrict__ Q,
        const uint32_t* __restrict__ K,
        const uint32_t* __restrict__ V,
        uint32_t* __restrict__ O)
{
    extern __shared__ uint32_t smw[];
    uint32_t* qs  = smw;
    uint32_t* kv0 = qs + 64*QS_STRIDE;
    uint32_t* ps  = qs;

    const int idx = blockIdx.x;
    const int qt  = NQT - 1 - (idx >> 4);     // longest tasks launch first
    const int sub = idx & 15;
    const int hh  = sub & 7, bb = sub >> 3;

    const int tid = threadIdx.x, warp = tid >> 5, lane = tid & 31;
    const int g = lane >> 2, tc = lane & 3;
    const int wq = warp * 16;

    const size_t base = ((size_t)bb*SEQ)*EMB + (size_t)hh*HEADD;
    const uint32_t kvb = smem_u32(kv0);

    const int tok0 = tid >> 4;
    const int d4s  = (tid & 15) << 2;

    #define ATT_ISSUE(kt_) do {                                                     \
        const uint32_t _so = (uint32_t)(((kt_) & 1) * KV_WORDS * 4);                \
        _Pragma("unroll")                                                           \
        for (int i = 0; i < 8; i++) {                                               \
            int _tok = tok0 + i*8;                                                  \
            CP_ASYNC16(kvb + _so + (uint32_t)(_tok*KS_STRIDE + d4s)*4,              \
                       &K[base + (size_t)((kt_)*64 + _tok)*EMB + d4s]);             \
            CP_ASYNC16(kvb + _so + (uint32_t)(64*KS_STRIDE + _tok*VS_STRIDE + d4s)*4,\
                       &V[base + (size_t)((kt_)*64 + _tok)*EMB + d4s]);             \
        }                                                                           \
    } while (0)

    const int nkt = qt + 1;

    // ---- stage Q tile ----
    #pragma unroll
    for (int i = 0; i < 8; i++) {
        int f   = i*128 + tid;
        int row = f >> 4, d4 = (f & 15) << 2;
        *(uint4*)&qs[row*QS_STRIDE + d4] =
            *(const uint4*)&Q[base + (size_t)(qt*64 + row)*EMB + d4];
    }
    ATT_ISSUE(0); CP_COMMIT();
    __syncthreads();

    uint32_t qf[8][4];
    #pragma unroll
    for (int ki = 0; ki < 8; ki++) {
        int k0 = ki*8;
        qf[ki][0] = qs[(wq+g  )*QS_STRIDE + k0 + tc];
        qf[ki][1] = qs[(wq+g+8)*QS_STRIDE + k0 + tc];
        qf[ki][2] = qs[(wq+g  )*QS_STRIDE + k0 + tc + 4];
        qf[ki][3] = qs[(wq+g+8)*QS_STRIDE + k0 + tc + 4];
    }

    float o[8][4];
    #pragma unroll
    for (int nt = 0; nt < 8; nt++)
        #pragma unroll
        for (int j = 0; j < 4; j++) o[nt][j] = 0.f;
    float m0 = -1e30f, m1 = -1e30f, l0 = 0.f, l1 = 0.f;

    for (int kt = 0; kt < nkt; kt++) {
        if (kt + 1 < nkt) { ATT_ISSUE(kt + 1); CP_COMMIT(); CP_WAIT1(); }
        else              { CP_WAIT0(); }
        __syncthreads();

        const uint32_t* ks = kv0 + (kt & 1)*KV_WORDS;
        const uint32_t* vs = ks + 64*KS_STRIDE;

        float sc[8][4];
        #pragma unroll
        for (int nt = 0; nt < 8; nt++)
            #pragma unroll
            for (int j = 0; j < 4; j++) sc[nt][j] = 0.f;

        #pragma unroll
        for (int ki = 0; ki < 8; ki++) {
            int k0 = ki*8;
            uint32_t bf[8][2];
            #pragma unroll
            for (int nt = 0; nt < 8; nt++) {
                int nb = nt*8 + g;
                bf[nt][0] = ks[nb*KS_STRIDE + k0 + tc];
                bf[nt][1] = ks[nb*KS_STRIDE + k0 + tc + 4];
            }
            #pragma unroll
            for (int nt = 0; nt < 8; nt++)
                mma_tf32(sc[nt], qf[ki], bf[nt]);
        }

        if (kt >= qt) {
            const int row0 = qt*64 + wq + g;
            #pragma unroll
            for (int nt = 0; nt < 8; nt++) {
                int c0 = kt*64 + nt*8 + 2*tc;
                if (c0     > row0    ) sc[nt][0] = -1e30f;
                if (c0 + 1 > row0    ) sc[nt][1] = -1e30f;
                if (c0     > row0 + 8) sc[nt][2] = -1e30f;
                if (c0 + 1 > row0 + 8) sc[nt][3] = -1e30f;
            }
        }

        float r0 = -1e30f, r1 = -1e30f;
        #pragma unroll
        for (int nt = 0; nt < 8; nt++) {
            r0 = fmaxf(r0, fmaxf(sc[nt][0], sc[nt][1]));
            r1 = fmaxf(r1, fmaxf(sc[nt][2], sc[nt][3]));
        }
        r0 = fmaxf(r0, __shfl_xor_sync(0xffffffffu, r0, 1));
        r0 = fmaxf(r0, __shfl_xor_sync(0xffffffffu, r0, 2));
        r1 = fmaxf(r1, __shfl_xor_sync(0xffffffffu, r1, 1));
        r1 = fmaxf(r1, __shfl_xor_sync(0xffffffffu, r1, 2));

        float mn0 = fmaxf(m0, r0), mn1 = fmaxf(m1, r1);
        float cor0 = __expf(m0 - mn0), cor1 = __expf(m1 - mn1);
        m0 = mn0; m1 = mn1;
        l0 *= cor0; l1 *= cor1;
        #pragma unroll
        for (int nt = 0; nt < 8; nt++) {
            o[nt][0] *= cor0; o[nt][1] *= cor0;
            o[nt][2] *= cor1; o[nt][3] *= cor1;
        }

        float s0 = 0.f, s1 = 0.f;
        #pragma unroll
        for (int nt = 0; nt < 8; nt++) {
            float p00 = __expf(sc[nt][0] - mn0);
            float p01 = __expf(sc[nt][1] - mn0);
            float p10 = __expf(sc[nt][2] - mn1);
            float p11 = __expf(sc[nt][3] - mn1);
            s0 += p00 + p01; s1 += p10 + p11;
            int col = nt*8 + 2*tc;
            ps[(wq+g  )*PS_STRIDE + col    ] = f2tf(p00);
            ps[(wq+g  )*PS_STRIDE + col + 1] = f2tf(p01);
            ps[(wq+g+8)*PS_STRIDE + col    ] = f2tf(p10);
            ps[(wq+g+8)*PS_STRIDE + col + 1] = f2tf(p11);
        }
        s0 += __shfl_xor_sync(0xffffffffu, s0, 1);
        s0 += __shfl_xor_sync(0xffffffffu, s0, 2);
        s1 += __shfl_xor_sync(0xffffffffu, s1, 1);
        s1 += __shfl_xor_sync(0xffffffffu, s1, 2);
        l0 += s0; l1 += s1;
        __syncwarp();

        #pragma unroll
        for (int ki = 0; ki < 8; ki++) {
            int k0 = ki*8;
            uint32_t af[4];
            af[0] = ps[(wq+g  )*PS_STRIDE + k0 + tc];
            af[1] = ps[(wq+g+8)*PS_STRIDE + k0 + tc];
            af[2] = ps[(wq+g  )*PS_STRIDE + k0 + tc + 4];
            af[3] = ps[(wq+g+8)*PS_STRIDE + k0 + tc + 4];
            uint32_t bf[8][2];
            #pragma unroll
            for (int nt = 0; nt < 8; nt++) {
                int nb = nt*8 + g;
                bf[nt][0] = vs[(k0 + tc    )*VS_STRIDE + nb];
                bf[nt][1] = vs[(k0 + tc + 4)*VS_STRIDE + nb];
            }
            #pragma unroll
            for (int nt = 0; nt < 8; nt++)
                mma_tf32(o[nt], af, bf[nt]);
        }
        __syncthreads();
    }

    float inv0 = 1.0f / l0, inv1 = 1.0f / l1;
    const int row0 = qt*64 + wq + g;
    #pragma unroll
    for (int nt = 0; nt < 8; nt++) {
        int d = nt*8 + 2*tc;
        uint2 a = { f2tf(o[nt][0]*inv0), f2tf(o[nt][1]*inv0) };
        *(uint2*)&O[base + (size_t)row0*EMB + d] = a;
        uint2 b = { f2tf(o[nt][2]*inv1), f2tf(o[nt][3]*inv1) };
        *(uint2*)&O[base + (size_t)(row0+8)*EMB + d] = b;
    }
    #undef ATT_ISSUE
}

// ---------------- orchestration ----------------
extern "C" void kernel_launch(void* const* d_in, const int* in_sizes, int n_in,
                              void* d_out, int out_size)
{
    (void)in_sizes; (void)n_in;
    const int*   x       = (const int*)  d_in[0];
    const float* tok_emb = (const float*)d_in[1];
    const float* pos_emb = (const float*)d_in[2];
    const float* Wq   = (const float*)d_in[3];
    const float* bq   = (const float*)d_in[4];
    const float* Wk   = (const float*)d_in[5];
    const float* bk   = (const float*)d_in[6];
    const float* Wv   = (const float*)d_in[7];
    const float* bv   = (const float*)d_in[8];
    const float* Wo   = (const float*)d_in[9];
    const float* bo   = (const float*)d_in[10];
    const float* ln1s = (const float*)d_in[11];
    const float* ln1b = (const float*)d_in[12];
    const float* ln2s = (const float*)d_in[13];
    const float* ln2b = (const float*)d_in[14];
    const float* W1   = (const float*)d_in[15];
    const float* b1   = (const float*)d_in[16];
    const float* W2   = (const float*)d_in[17];
    const float* b2   = (const float*)d_in[18];
    const float* Wout = (const float*)d_in[19];
    const float* bout = (const float*)d_in[20];
    float* out = (float*)d_out;
    (void)out_size;

    float *h; uint32_t *y, *q, *k, *v, *o, *ff, *htf, *wtf;
    cudaGetSymbolAddress((void**)&h,   g_h);
    cudaGetSymbolAddress((void**)&y,   g_y);
    cudaGetSymbolAddress((void**)&q,   g_q);
    cudaGetSymbolAddress((void**)&k,   g_k);
    cudaGetSymbolAddress((void**)&v,   g_v);
    cudaGetSymbolAddress((void**)&o,   g_o);
    cudaGetSymbolAddress((void**)&ff,  g_ff);
    cudaGetSymbolAddress((void**)&htf, g_htf);
    cudaGetSymbolAddress((void**)&wtf, g_wtf);

    cudaFuncSetAttribute(gemm128<false,false,0>,
        cudaFuncAttributeMaxDynamicSharedMemorySize, GEMM_SMEM_BYTES);
    cudaFuncSetAttribute(gemm128<true,false,1>,
        cudaFuncAttributeMaxDynamicSharedMemorySize, GEMM_SMEM_BYTES);
    cudaFuncSetAttribute(qkv_gemm,
        cudaFuncAttributeMaxDynamicSharedMemorySize, GEMM_SMEM_BYTES);
    cudaFuncSetAttribute(gemm64<false,true,0>,
        cudaFuncAttributeMaxDynamicSharedMemorySize, GEMM64_SMEM_BYTES);
    cudaFuncSetAttribute(gemm64<false,true,1>,
        cudaFuncAttributeMaxDynamicSharedMemorySize, GEMM64_SMEM_BYTES);
    cudaFuncSetAttribute(attn_mma_kernel,
        cudaFuncAttributeMaxDynamicSharedMemorySize, ATT_SMEM_BYTES);

    // launch 1: fused weight conversion + embedding
    prep_kernel<<<EMBED_BLOCKS + CVT_BLOCKS, 256>>>(
        Wq, Wk, Wv, Wo, W1, W2, Wout, wtf, x, tok_emb, pos_emb, h);

    const int M = BT;

    for (int i = 0; i < NLAYER; i++) {
        const uint32_t* Wqi = wtf + OFF_WQ + (size_t)i*EMB*EMB;
        const uint32_t* Wki = wtf + OFF_WK + (size_t)i*EMB*EMB;
        const uint32_t* Wvi = wtf + OFF_WV + (size_t)i*EMB*EMB;
        const uint32_t* Woi = wtf + OFF_WO + (size_t)i*EMB*EMB;
        const uint32_t* W1i = wtf + OFF_W1 + (size_t)i*EMB*FFDIM;
        const uint32_t* W2i = wtf + OFF_W2 + (size_t)i*FFDIM*EMB;

        ln_kernel<<<BT/8, 256>>>(h, ln1s + i*EMB, ln1b + i*EMB, y);

        qkv_gemm<<<dim3(12, M/128), 256, GEMM_SMEM_BYTES>>>(
            y, Wqi, Wki, Wvi, bq + i*EMB, bk + i*EMB, bv + i*EMB, q, k, v);

        attn_mma_kernel<<<NQT*NHEAD*BATCH, 128, ATT_SMEM_BYTES>>>(q, k, v, o);

        gemm64<false,true,0><<<dim3(EMB/128, M/64), 256, GEMM64_SMEM_BYTES>>>(
            M, EMB, EMB, o, Woi, bo + i*EMB, h, nullptr);

        ln_kernel<<<BT/8, 256>>>(h, ln2s + i*EMB, ln2b + i*EMB, y);

        gemm128<true,false,1><<<dim3(FFDIM/128, M/128), 256, GEMM_SMEM_BYTES>>>(
            M, FFDIM, EMB, y, W1i, b1 + i*FFDIM, nullptr, ff);

        if (i < NLAYER - 1) {
            gemm64<false,true,0><<<dim3(EMB/128, M/64), 256, GEMM64_SMEM_BYTES>>>(
                M, EMB, FFDIM, ff, W2i, b2 + i*EMB, h, nullptr);
        } else {
            gemm64<false,true,1><<<dim3(EMB/128, M/64), 256, GEMM64_SMEM_BYTES>>>(
                M, EMB, FFDIM, ff, W2i, b2 + i*EMB, h, htf);
        }
    }

    gemm128<false,false,0><<<dim3(VOCAB/128, M/128), 256, GEMM_SMEM_BYTES>>>(
        M, VOCAB, EMB, htf, wtf + OFF_WOUT, bout, out, nullptr);
}